// round 9
// baseline (speedup 1.0000x reference)
#include <cuda_runtime.h>
#include <cuda_bf16.h>
#include <math.h>
#include <cstdint>

#define BB 2
#define SS 2048
#define DD 1024
#define HH 16
#define DH 64
#define MROWS (BB*SS)   // 4096

// fp32 scratch (projection outputs)
__device__ float g_Q[BB*HH*SS*DH];    // Q natural [bh][s][d] (also the values)
__device__ float g_K[BB*HH*SS*DH];    // K raw     [bh][s][d]
// bf16 split operands for attention
__device__ __nv_bfloat16 g_Khi[BB*HH*SS*DH];  // fused K, natural [bh][s][d]
__device__ __nv_bfloat16 g_Klo[BB*HH*SS*DH];
__device__ __nv_bfloat16 g_Vhi[BB*HH*DH*SS];  // V(=Q) transposed [bh][d][s]
__device__ __nv_bfloat16 g_Vlo[BB*HH*DH*SS];
// bf16 split operands for projections
__device__ __nv_bfloat16 g_Ahi[MROWS*DD];     // hidden_states [m][k]
__device__ __nv_bfloat16 g_Alo[MROWS*DD];
__device__ __nv_bfloat16 g_Wthi[2*DD*DD];     // W transposed [w][n][k]
__device__ __nv_bfloat16 g_Wtlo[2*DD*DD];

__device__ __forceinline__ float logsig(float x) {
    return fminf(x, 0.0f) - log1pf(expf(-fabsf(x)));
}

// ---- mma.sync / ldmatrix helpers (sm_80+ PTX) -----------------------------
__device__ __forceinline__ uint32_t smem_u32(const void* p) {
    uint32_t a;
    asm("{ .reg .u64 t; cvta.to.shared.u64 t, %1; cvt.u32.u64 %0, t; }" : "=r"(a) : "l"(p));
    return a;
}
__device__ __forceinline__ void ldsm4(uint32_t* r, uint32_t addr) {
    asm volatile("ldmatrix.sync.aligned.m8n8.x4.shared.b16 {%0,%1,%2,%3}, [%4];"
        : "=r"(r[0]), "=r"(r[1]), "=r"(r[2]), "=r"(r[3]) : "r"(addr));
}
__device__ __forceinline__ void mma16816(float* c, const uint32_t* a, const uint32_t* b) {
    asm volatile(
        "mma.sync.aligned.m16n8k16.row.col.f32.bf16.bf16.f32 "
        "{%0,%1,%2,%3}, {%4,%5,%6,%7}, {%8,%9}, {%0,%1,%2,%3};"
        : "+f"(c[0]), "+f"(c[1]), "+f"(c[2]), "+f"(c[3])
        : "r"(a[0]), "r"(a[1]), "r"(a[2]), "r"(a[3]), "r"(b[0]), "r"(b[1]));
}
__device__ __forceinline__ void split_pair(float x, float y, uint32_t& hi, uint32_t& lo) {
    __nv_bfloat16 hx = __float2bfloat16(x), hy = __float2bfloat16(y);
    __nv_bfloat16 lx = __float2bfloat16(x - __bfloat162float(hx));
    __nv_bfloat16 ly = __float2bfloat16(y - __bfloat162float(hy));
    __nv_bfloat162 hv; hv.x = hx; hv.y = hy;
    __nv_bfloat162 lv; lv.x = lx; lv.y = ly;
    hi = *(const uint32_t*)&hv;
    lo = *(const uint32_t*)&lv;
}

// ---------------------------------------------------------------------------
// split_hs: hidden_states fp32 [m][k] -> bf16 hi/lo. 8 elems/thread.
// ---------------------------------------------------------------------------
__global__ __launch_bounds__(256) void split_hs(const float* __restrict__ hs)
{
    const int i8 = blockIdx.x * 256 + threadIdx.x;
    float4 a = ((const float4*)hs)[i8*2];
    float4 b = ((const float4*)hs)[i8*2+1];
    float f[8] = { a.x,a.y,a.z,a.w, b.x,b.y,b.z,b.w };
    __nv_bfloat16 hi[8], lo[8];
    #pragma unroll
    for (int j = 0; j < 8; j++) {
        hi[j] = __float2bfloat16(f[j]);
        lo[j] = __float2bfloat16(f[j] - __bfloat162float(hi[j]));
    }
    ((uint4*)g_Ahi)[i8] = *(const uint4*)hi;
    ((uint4*)g_Alo)[i8] = *(const uint4*)lo;
}

// ---------------------------------------------------------------------------
// split_w: W fp32 [k][n] -> Wt bf16 hi/lo [n][k]. 64x64 tiles, 256 threads.
// z selects weight (0=Wq, 1=Wk).
// ---------------------------------------------------------------------------
__global__ __launch_bounds__(256) void split_w(
    const float* __restrict__ Wq, const float* __restrict__ Wk)
{
    __shared__ float tw[64][65];
    const int wsel = blockIdx.z;
    const float* W = wsel ? Wk : Wq;
    const int k0 = blockIdx.y * 64;
    const int n0 = blockIdx.x * 64;
    const int tid = threadIdx.x;

    #pragma unroll
    for (int i = 0; i < 4; i++) {
        int idx4 = tid + i * 256;        // 0..1023
        int row  = idx4 >> 4;            // k within tile
        int c    = (idx4 & 15) * 4;      // n
        float4 v = *(const float4*)&W[(size_t)(k0 + row) * DD + n0 + c];
        tw[row][c+0] = v.x; tw[row][c+1] = v.y; tw[row][c+2] = v.z; tw[row][c+3] = v.w;
    }
    __syncthreads();

    const int n  = tid >> 2;             // 0..63
    const int kq = (tid & 3) * 16;
    __nv_bfloat16 hi[16], lo[16];
    #pragma unroll
    for (int c = 0; c < 16; c++) {
        float v = tw[kq+c][n];
        hi[c] = __float2bfloat16(v);
        lo[c] = __float2bfloat16(v - __bfloat162float(hi[c]));
    }
    size_t off = (size_t)wsel*DD*DD + (size_t)(n0 + n)*DD + k0 + kq;
    *(uint4*)(g_Wthi + off)     = *(const uint4*)hi;
    *(uint4*)(g_Wthi + off + 8) = *(const uint4*)(hi + 8);
    *(uint4*)(g_Wtlo + off)     = *(const uint4*)lo;
    *(uint4*)(g_Wtlo + off + 8) = *(const uint4*)(lo + 8);
}

// ---------------------------------------------------------------------------
// Projection GEMM on tensor pipe: C = A @ W + bias, 3-product bf16 split.
// Block = 128m x 128n, 8 warps (warp = 16m x 128n). k-tiles of 64.
// smem: AH[128][64] | AL | BH[128n][64k] | BL  (XOR-swizzled 128B rows) = 64KB
// z selects (Wq -> g_Q) / (Wk -> g_K).
// ---------------------------------------------------------------------------
#define PG_AH 0
#define PG_AL 16384
#define PG_BH 32768
#define PG_BL 49152
#define PG_SMEM 65536

__global__ __launch_bounds__(256) void proj_gemm(
    const float* __restrict__ bq, const float* __restrict__ bk)
{
    extern __shared__ char smem[];
    const uint32_t sb = smem_u32(smem);
    const int tid  = threadIdx.x;
    const int w    = tid >> 5;
    const int lane = tid & 31;
    const int wsel = blockIdx.z;
    const int m0 = blockIdx.y * 128;
    const int n0 = blockIdx.x * 128;

    const float* bias = wsel ? bk : bq;
    float* dst = wsel ? g_K : g_Q;
    const uint4* Ahi = (const uint4*)g_Ahi;
    const uint4* Alo = (const uint4*)g_Alo;
    const uint4* Bhi = (const uint4*)(g_Wthi + (size_t)wsel * DD * DD);
    const uint4* Blo = (const uint4*)(g_Wtlo + (size_t)wsel * DD * DD);

    const int row_off = (lane & 7) + ((lane & 16) >> 1);  // B-side geometry
    const int khalf   = (lane >> 3) & 1;
    const int arow    = lane & 15;                        // A-side geometry
    const int ahalf   = (lane >> 4) & 1;

    float acc[16][4];
    #pragma unroll
    for (int j = 0; j < 16; j++)
        #pragma unroll
        for (int c = 0; c < 4; c++) acc[j][c] = 0.0f;

    for (int t = 0; t < 16; t++) {
        const int k0 = t * 64;          // k tile (64 = 8 uint4 per row)
        if (t > 0) __syncthreads();

        #pragma unroll
        for (int i = 0; i < 4; i++) {
            int c = tid + i * 256;              // 0..1023
            int r = c >> 3, ck = c & 7;
            uint32_t off = (uint32_t)(r * 128 + ((ck ^ (r & 7)) << 4));
            int asrc = (m0 + r) * (DD/8) + k0/8 + ck;
            *(uint4*)(smem + PG_AH + off) = Ahi[asrc];
            *(uint4*)(smem + PG_AL + off) = Alo[asrc];
            int bsrc = (n0 + r) * (DD/8) + k0/8 + ck;
            *(uint4*)(smem + PG_BH + off) = Bhi[bsrc];
            *(uint4*)(smem + PG_BL + off) = Blo[bsrc];
        }
        __syncthreads();

        #pragma unroll
        for (int ks = 0; ks < 4; ks++) {
            // A fragments (hi + lo)
            int ar = w * 16 + arow;
            int ac = ks * 2 + ahalf;
            uint32_t aoff = (uint32_t)(ar * 128 + ((ac ^ (ar & 7)) << 4));
            uint32_t ah4[4], al4[4];
            ldsm4(ah4, sb + PG_AH + aoff);
            ldsm4(al4, sb + PG_AL + aoff);

            #pragma unroll
            for (int jp = 0; jp < 8; jp++) {
                int br = jp * 16 + row_off;
                int bc = ks * 2 + khalf;
                uint32_t boff = (uint32_t)(br * 128 + ((bc ^ (br & 7)) << 4));
                uint32_t bh4[4], bl4[4];
                ldsm4(bh4, sb + PG_BH + boff);
                ldsm4(bl4, sb + PG_BL + boff);
                mma16816(acc[2*jp],   ah4, bh4);
                mma16816(acc[2*jp],   al4, bh4);
                mma16816(acc[2*jp],   ah4, bl4);
                mma16816(acc[2*jp+1], ah4, bh4 + 2);
                mma16816(acc[2*jp+1], al4, bh4 + 2);
                mma16816(acc[2*jp+1], ah4, bl4 + 2);
            }
        }
    }

    // epilogue: add bias, scatter to [b][h][s][d]
    const int r0  = m0 + w * 16 + (lane >> 2);
    const int cq  = (lane & 3) * 2;
    const int b0  = r0 >> 11,      s0 = r0 & (SS - 1);
    const int b1  = (r0+8) >> 11,  s1 = (r0+8) & (SS - 1);
    #pragma unroll
    for (int j = 0; j < 16; j++) {
        int n = n0 + j * 8 + cq;
        int h = n >> 6, d = n & (DH - 1);
        float2 w0 = make_float2(acc[j][0] + bias[n], acc[j][1] + bias[n+1]);
        float2 w1 = make_float2(acc[j][2] + bias[n], acc[j][3] + bias[n+1]);
        *(float2*)&dst[(((size_t)b0 * HH + h) * SS + s0) * DH + d] = w0;
        *(float2*)&dst[(((size_t)b1 * HH + h) * SS + s1) * DH + d] = w1;
    }
}

// ---------------------------------------------------------------------------
// Pointwise fused K -> bf16 hi/lo split (natural layout). 8 elems/thread.
// ---------------------------------------------------------------------------
__global__ __launch_bounds__(128) void split_k()
{
    const int i8 = blockIdx.x * 128 + threadIdx.x;
    const float4* Q = (const float4*)g_Q;
    const float4* K = (const float4*)g_K;
    float4 qa = Q[i8*2], qb = Q[i8*2+1];
    float4 ka = K[i8*2], kb = K[i8*2+1];
    float f[8] = {
        logsig(logsig(qa.x)+qa.x+ka.x), logsig(logsig(qa.y)+qa.y+ka.y),
        logsig(logsig(qa.z)+qa.z+ka.z), logsig(logsig(qa.w)+qa.w+ka.w),
        logsig(logsig(qb.x)+qb.x+kb.x), logsig(logsig(qb.y)+qb.y+kb.y),
        logsig(logsig(qb.z)+qb.z+kb.z), logsig(logsig(qb.w)+qb.w+kb.w) };
    __nv_bfloat16 hi[8], lo[8];
    #pragma unroll
    for (int j = 0; j < 8; j++) {
        hi[j] = __float2bfloat16(f[j]);
        lo[j] = __float2bfloat16(f[j] - __bfloat162float(hi[j]));
    }
    ((uint4*)g_Khi)[i8] = *(const uint4*)hi;
    ((uint4*)g_Klo)[i8] = *(const uint4*)lo;
}

// ---------------------------------------------------------------------------
// V(=Q) transpose to [bh][d][s] with bf16 hi/lo split. 64x64 tiles, 256 thr.
// ---------------------------------------------------------------------------
__global__ __launch_bounds__(256) void transpose_v()
{
    __shared__ float tq[64][65];
    const int bh = blockIdx.y;
    const int s0 = blockIdx.x * 64;
    const int tid = threadIdx.x;

    const float4* Qsrc = (const float4*)(g_Q + (size_t)bh*SS*DH + (size_t)s0*DH);
    #pragma unroll
    for (int i = 0; i < 4; i++) {
        int idx4 = tid + i * 256;
        int row  = idx4 >> 4;
        int c    = (idx4 & 15) * 4;
        float4 q = Qsrc[idx4];
        tq[row][c+0] = q.x; tq[row][c+1] = q.y; tq[row][c+2] = q.z; tq[row][c+3] = q.w;
    }
    __syncthreads();

    const int d  = tid >> 2;
    const int sq = (tid & 3) * 16;
    __nv_bfloat16 hi[16], lo[16];
    #pragma unroll
    for (int c = 0; c < 16; c++) {
        float v = tq[sq+c][d];
        hi[c] = __float2bfloat16(v);
        lo[c] = __float2bfloat16(v - __bfloat162float(hi[c]));
    }
    size_t off = (size_t)bh*DH*SS + (size_t)d*SS + s0 + sq;
    *(uint4*)(g_Vhi + off)     = *(const uint4*)hi;
    *(uint4*)(g_Vhi + off + 8) = *(const uint4*)(hi + 8);
    *(uint4*)(g_Vlo + off)     = *(const uint4*)lo;
    *(uint4*)(g_Vlo + off + 8) = *(const uint4*)(lo + 8);
}

// ---------------------------------------------------------------------------
// mma.sync flash attention (unchanged — known good, 702us total).
// ---------------------------------------------------------------------------
#define SM_KH 0
#define SM_KL 16384
#define SM_VH 32768
#define SM_VL 49152
#define ATTN_SMEM 65536

__global__ __launch_bounds__(256, 1) void attn(
    const int* __restrict__ mask, float* __restrict__ out)
{
    extern __shared__ char smem[];
    const uint32_t sb = smem_u32(smem);
    const int tid  = threadIdx.x;
    const int w    = tid >> 5;
    const int lane = tid & 31;
    const int bh = blockIdx.y;
    const int b  = bh >> 4;
    const int h  = bh & (HH - 1);
    const int q0 = blockIdx.x * 128;

    const int row_off = (lane & 7) + ((lane & 16) >> 1);
    const int khalf   = (lane >> 3) & 1;

    {
        float* Qs = (float*)smem;
        const float* src = g_Q + ((size_t)bh * SS + q0) * DH;
        #pragma unroll
        for (int i = 0; i < 8; i++) {
            int idx4 = tid + i * 256;
            ((float4*)Qs)[idx4] = ((const float4*)src)[idx4];
        }
        __syncthreads();
    }

    const int r0 = lane >> 2;
    const int cq = (lane & 3) * 2;
    uint32_t qh[4][4], ql[4][4];
    {
        const float* Qs = (const float*)smem;
        const int m0 = w * 16 + r0;
        #pragma unroll
        for (int ks = 0; ks < 4; ks++) {
            int c0 = ks * 16 + cq;
            float x0 = Qs[m0*64 + c0]     * -0.125f, y0 = Qs[m0*64 + c0 + 1]     * -0.125f;
            float x1 = Qs[(m0+8)*64 + c0] * -0.125f, y1 = Qs[(m0+8)*64 + c0 + 1] * -0.125f;
            float x2 = Qs[m0*64 + c0 + 8] * -0.125f, y2 = Qs[m0*64 + c0 + 9]     * -0.125f;
            float x3 = Qs[(m0+8)*64 + c0 + 8] * -0.125f, y3 = Qs[(m0+8)*64 + c0 + 9] * -0.125f;
            split_pair(x0, y0, qh[ks][0], ql[ks][0]);
            split_pair(x1, y1, qh[ks][1], ql[ks][1]);
            split_pair(x2, y2, qh[ks][2], ql[ks][2]);
            split_pair(x3, y3, qh[ks][3], ql[ks][3]);
        }
    }

    const bool mq0 = (mask[b * SS + q0 + w*16 + r0]     == 0);
    const bool mq1 = (mask[b * SS + q0 + w*16 + r0 + 8] == 0);

    float l0 = 0.0f, l1 = 0.0f;
    float oacc[8][4];
    #pragma unroll
    for (int j = 0; j < 8; j++)
        #pragma unroll
        for (int c = 0; c < 4; c++) oacc[j][c] = 0.0f;

    const uint4* Khi = (const uint4*)(g_Khi + (size_t)bh * SS * DH);
    const uint4* Klo = (const uint4*)(g_Klo + (size_t)bh * SS * DH);
    const uint4* Vhi = (const uint4*)(g_Vhi + (size_t)bh * DH * SS);
    const uint4* Vlo = (const uint4*)(g_Vlo + (size_t)bh * DH * SS);

    for (int t = 0; t < 16; t++) {
        const int t0 = t * 128;
        __syncthreads();

        #pragma unroll
        for (int i = 0; i < 4; i++) {
            int c = tid + i * 256;
            int rk = c >> 3, ck = c & 7;
            uint32_t kd = (uint32_t)(rk * 128 + ((ck ^ (rk & 7)) << 4));
            int ksrc = (t0 + rk) * 8 + ck;
            *(uint4*)(smem + SM_KH + kd) = Khi[ksrc];
            *(uint4*)(smem + SM_KL + kd) = Klo[ksrc];
            int rv = c >> 4, cv = c & 15;
            uint32_t vd = (uint32_t)(rv * 256 + ((cv ^ (rv & 7)) << 4));
            int vsrc = rv * (SS/8) + t0/8 + cv;
            *(uint4*)(smem + SM_VH + vd) = Vhi[vsrc];
            *(uint4*)(smem + SM_VL + vd) = Vlo[vsrc];
        }
        __syncthreads();

        float sacc[16][4];
        #pragma unroll
        for (int j = 0; j < 16; j++)
            #pragma unroll
            for (int c = 0; c < 4; c++) sacc[j][c] = 0.0f;

        #pragma unroll
        for (int ks = 0; ks < 4; ks++) {
            #pragma unroll
            for (int jp = 0; jp < 8; jp++) {
                int row = jp * 16 + row_off;
                int chunk = ks * 2 + khalf;
                uint32_t off = (uint32_t)(row * 128 + ((chunk ^ (row & 7)) << 4));
                uint32_t bh4[4], bl4[4];
                ldsm4(bh4, sb + SM_KH + off);
                ldsm4(bl4, sb + SM_KL + off);
                mma16816(sacc[2*jp],   qh[ks], bh4);
                mma16816(sacc[2*jp],   ql[ks], bh4);
                mma16816(sacc[2*jp],   qh[ks], bl4);
                mma16816(sacc[2*jp+1], qh[ks], bh4 + 2);
                mma16816(sacc[2*jp+1], ql[ks], bh4 + 2);
                mma16816(sacc[2*jp+1], qh[ks], bl4 + 2);
            }
        }

        uint32_t phi[8][4], plo[8][4];
        #pragma unroll
        for (int kp = 0; kp < 8; kp++) {
            float p[8];
            #pragma unroll
            for (int half = 0; half < 2; half++) {
                const float* sc = sacc[2*kp + half];
                p[half*4+0] = __expf(mq0 ? 0.0f : sc[0]);
                p[half*4+1] = __expf(mq0 ? 0.0f : sc[1]);
                p[half*4+2] = __expf(mq1 ? 0.0f : sc[2]);
                p[half*4+3] = __expf(mq1 ? 0.0f : sc[3]);
            }
            l0 += p[0] + p[1] + p[4] + p[5];
            l1 += p[2] + p[3] + p[6] + p[7];
            split_pair(p[0], p[1], phi[kp][0], plo[kp][0]);
            split_pair(p[2], p[3], phi[kp][1], plo[kp][1]);
            split_pair(p[4], p[5], phi[kp][2], plo[kp][2]);
            split_pair(p[6], p[7], phi[kp][3], plo[kp][3]);
        }

        #pragma unroll
        for (int kp = 0; kp < 8; kp++) {
            #pragma unroll
            for (int jp = 0; jp < 4; jp++) {
                int row = jp * 16 + row_off;
                int chunk = kp * 2 + khalf;
                uint32_t off = (uint32_t)(row * 256 + ((chunk ^ (row & 7)) << 4));
                uint32_t vh4[4], vl4[4];
                ldsm4(vh4, sb + SM_VH + off);
                ldsm4(vl4, sb + SM_VL + off);
                mma16816(oacc[2*jp],   phi[kp], vh4);
                mma16816(oacc[2*jp],   plo[kp], vh4);
                mma16816(oacc[2*jp],   phi[kp], vl4);
                mma16816(oacc[2*jp+1], phi[kp], vh4 + 2);
                mma16816(oacc[2*jp+1], plo[kp], vh4 + 2);
                mma16816(oacc[2*jp+1], phi[kp], vl4 + 2);
            }
        }
    }

    l0 += __shfl_xor_sync(0xffffffffu, l0, 1);
    l0 += __shfl_xor_sync(0xffffffffu, l0, 2);
    l1 += __shfl_xor_sync(0xffffffffu, l1, 1);
    l1 += __shfl_xor_sync(0xffffffffu, l1, 2);
    const float inv0 = 1.0f / l0;
    const float inv1 = 1.0f / l1;

    const int s0 = q0 + w*16 + r0;
    float* o0 = out + ((size_t)b * SS + s0)     * (HH*DH) + h * DH;
    float* o1 = out + ((size_t)b * SS + s0 + 8) * (HH*DH) + h * DH;
    #pragma unroll
    for (int j = 0; j < 8; j++) {
        int col = j * 8 + cq;
        float2 w0 = make_float2(oacc[j][0] * inv0, oacc[j][1] * inv0);
        float2 w1 = make_float2(oacc[j][2] * inv1, oacc[j][3] * inv1);
        *(float2*)(o0 + col) = w0;
        *(float2*)(o1 + col) = w1;
    }
}

// ---------------------------------------------------------------------------
extern "C" void kernel_launch(void* const* d_in, const int* in_sizes, int n_in,
                              void* d_out, int out_size)
{
    const float* hs   = (const float*)d_in[0];
    const int*   mask = (const int*)  d_in[1];
    const float* Wq   = (const float*)d_in[2];
    const float* bq   = (const float*)d_in[3];
    const float* Wk   = (const float*)d_in[4];
    const float* bk   = (const float*)d_in[5];
    float* out = (float*)d_out;

    split_hs<<<(MROWS*DD) / (256 * 8), 256>>>(hs);          // 2048 blocks
    dim3 wgrid(DD / 64, DD / 64, 2);                        // (16,16,2)
    split_w<<<wgrid, 256>>>(Wq, Wk);

    cudaFuncSetAttribute(proj_gemm, cudaFuncAttributeMaxDynamicSharedMemorySize, PG_SMEM);
    dim3 pgrid(DD / 128, MROWS / 128, 2);                   // (8,32,2)
    proj_gemm<<<pgrid, 256, PG_SMEM>>>(bq, bk);

    split_k<<<(BB*HH*SS*DH) / (128 * 8), 128>>>();
    dim3 tgrid(SS / 64, BB * HH);
    transpose_v<<<tgrid, 256>>>();

    cudaFuncSetAttribute(attn, cudaFuncAttributeMaxDynamicSharedMemorySize, ATTN_SMEM);
    dim3 agrid(SS / 128, BB * HH);                          // (16,32)
    attn<<<agrid, 256, ATTN_SMEM>>>(mask, out);
}

// round 10
// speedup vs baseline: 1.6461x; 1.6461x over previous
#include <cuda_runtime.h>
#include <cuda_bf16.h>
#include <math.h>
#include <cstdint>

#define BB 2
#define SS 2048
#define DD 1024
#define HH 16
#define DH 64
#define MROWS (BB*SS)   // 4096

// fp32 scratch (projection outputs)
__device__ float g_Q[BB*HH*SS*DH];    // Q natural [bh][s][d] (also the values)
__device__ float g_K[BB*HH*SS*DH];    // K raw     [bh][s][d]
// bf16 split operands for attention
__device__ __nv_bfloat16 g_Khi[BB*HH*SS*DH];  // fused K, natural [bh][s][d]
__device__ __nv_bfloat16 g_Klo[BB*HH*SS*DH];
__device__ __nv_bfloat16 g_Vhi[BB*HH*DH*SS];  // V(=Q) transposed [bh][d][s]
__device__ __nv_bfloat16 g_Vlo[BB*HH*DH*SS];
// bf16 split operands for projections
__device__ __nv_bfloat16 g_Ahi[MROWS*DD];     // hidden_states [m][k]
__device__ __nv_bfloat16 g_Alo[MROWS*DD];
__device__ __nv_bfloat16 g_Wthi[2*DD*DD];     // W transposed [w][n][k]
__device__ __nv_bfloat16 g_Wtlo[2*DD*DD];

__device__ __forceinline__ float logsig(float x) {
    return fminf(x, 0.0f) - log1pf(expf(-fabsf(x)));
}

// ---- mma.sync / ldmatrix / cp.async helpers (sm_80+ PTX) ------------------
__device__ __forceinline__ uint32_t smem_u32(const void* p) {
    uint32_t a;
    asm("{ .reg .u64 t; cvta.to.shared.u64 t, %1; cvt.u32.u64 %0, t; }" : "=r"(a) : "l"(p));
    return a;
}
__device__ __forceinline__ void ldsm4(uint32_t* r, uint32_t addr) {
    asm volatile("ldmatrix.sync.aligned.m8n8.x4.shared.b16 {%0,%1,%2,%3}, [%4];"
        : "=r"(r[0]), "=r"(r[1]), "=r"(r[2]), "=r"(r[3]) : "r"(addr));
}
__device__ __forceinline__ void mma16816(float* c, const uint32_t* a, const uint32_t* b) {
    asm volatile(
        "mma.sync.aligned.m16n8k16.row.col.f32.bf16.bf16.f32 "
        "{%0,%1,%2,%3}, {%4,%5,%6,%7}, {%8,%9}, {%0,%1,%2,%3};"
        : "+f"(c[0]), "+f"(c[1]), "+f"(c[2]), "+f"(c[3])
        : "r"(a[0]), "r"(a[1]), "r"(a[2]), "r"(a[3]), "r"(b[0]), "r"(b[1]));
}
__device__ __forceinline__ void split_pair(float x, float y, uint32_t& hi, uint32_t& lo) {
    __nv_bfloat16 hx = __float2bfloat16(x), hy = __float2bfloat16(y);
    __nv_bfloat16 lx = __float2bfloat16(x - __bfloat162float(hx));
    __nv_bfloat16 ly = __float2bfloat16(y - __bfloat162float(hy));
    __nv_bfloat162 hv; hv.x = hx; hv.y = hy;
    __nv_bfloat162 lv; lv.x = lx; lv.y = ly;
    hi = *(const uint32_t*)&hv;
    lo = *(const uint32_t*)&lv;
}
__device__ __forceinline__ void cpasync16(uint32_t saddr, const void* g) {
    asm volatile("cp.async.cg.shared.global [%0], [%1], 16;" :: "r"(saddr), "l"(g));
}
#define CP_COMMIT()     asm volatile("cp.async.commit_group;" ::: "memory")
#define CP_WAIT(n)      asm volatile("cp.async.wait_group %0;" :: "n"(n) : "memory")

// ---------------------------------------------------------------------------
// split_hs: hidden_states fp32 [m][k] -> bf16 hi/lo. 8 elems/thread.
// ---------------------------------------------------------------------------
__global__ __launch_bounds__(256) void split_hs(const float* __restrict__ hs)
{
    const int i8 = blockIdx.x * 256 + threadIdx.x;
    float4 a = ((const float4*)hs)[i8*2];
    float4 b = ((const float4*)hs)[i8*2+1];
    float f[8] = { a.x,a.y,a.z,a.w, b.x,b.y,b.z,b.w };
    __nv_bfloat16 hi[8], lo[8];
    #pragma unroll
    for (int j = 0; j < 8; j++) {
        hi[j] = __float2bfloat16(f[j]);
        lo[j] = __float2bfloat16(f[j] - __bfloat162float(hi[j]));
    }
    ((uint4*)g_Ahi)[i8] = *(const uint4*)hi;
    ((uint4*)g_Alo)[i8] = *(const uint4*)lo;
}

// ---------------------------------------------------------------------------
// split_w: W fp32 [k][n] -> Wt bf16 hi/lo [n][k]. 64x64 tiles, 256 threads.
// ---------------------------------------------------------------------------
__global__ __launch_bounds__(256) void split_w(
    const float* __restrict__ Wq, const float* __restrict__ Wk)
{
    __shared__ float tw[64][65];
    const int wsel = blockIdx.z;
    const float* W = wsel ? Wk : Wq;
    const int k0 = blockIdx.y * 64;
    const int n0 = blockIdx.x * 64;
    const int tid = threadIdx.x;

    #pragma unroll
    for (int i = 0; i < 4; i++) {
        int idx4 = tid + i * 256;        // 0..1023
        int row  = idx4 >> 4;            // k within tile
        int c    = (idx4 & 15) * 4;      // n
        float4 v = *(const float4*)&W[(size_t)(k0 + row) * DD + n0 + c];
        tw[row][c+0] = v.x; tw[row][c+1] = v.y; tw[row][c+2] = v.z; tw[row][c+3] = v.w;
    }
    __syncthreads();

    const int n  = tid >> 2;             // 0..63
    const int kq = (tid & 3) * 16;
    __nv_bfloat16 hi[16], lo[16];
    #pragma unroll
    for (int c = 0; c < 16; c++) {
        float v = tw[kq+c][n];
        hi[c] = __float2bfloat16(v);
        lo[c] = __float2bfloat16(v - __bfloat162float(hi[c]));
    }
    size_t off = (size_t)wsel*DD*DD + (size_t)(n0 + n)*DD + k0 + kq;
    *(uint4*)(g_Wthi + off)     = *(const uint4*)hi;
    *(uint4*)(g_Wthi + off + 8) = *(const uint4*)(hi + 8);
    *(uint4*)(g_Wtlo + off)     = *(const uint4*)lo;
    *(uint4*)(g_Wtlo + off + 8) = *(const uint4*)(lo + 8);
}

// ---------------------------------------------------------------------------
// Projection GEMM on tensor pipe, 2-stage cp.async pipeline.
// Block = 128m x 128n, 8 warps. k-tiles of 64.
// smem: 2 stages x (AH | AL | BH | BL), each 128x64 bf16 = 16KB -> 128KB.
// ---------------------------------------------------------------------------
#define PG_AH 0
#define PG_AL 16384
#define PG_BH 32768
#define PG_BL 49152
#define PG_STAGE 65536
#define PG_SMEM (2*PG_STAGE)

__global__ __launch_bounds__(256) void proj_gemm(
    const float* __restrict__ bq, const float* __restrict__ bk)
{
    extern __shared__ char smem[];
    const uint32_t sb = smem_u32(smem);
    const int tid  = threadIdx.x;
    const int w    = tid >> 5;
    const int lane = tid & 31;
    const int wsel = blockIdx.z;
    const int m0 = blockIdx.y * 128;
    const int n0 = blockIdx.x * 128;

    const float* bias = wsel ? bk : bq;
    float* dst = wsel ? g_K : g_Q;
    const uint4* Ahi = (const uint4*)g_Ahi;
    const uint4* Alo = (const uint4*)g_Alo;
    const uint4* Bhi = (const uint4*)(g_Wthi + (size_t)wsel * DD * DD);
    const uint4* Blo = (const uint4*)(g_Wtlo + (size_t)wsel * DD * DD);

    const int row_off = (lane & 7) + ((lane & 16) >> 1);  // B-side geometry
    const int khalf   = (lane >> 3) & 1;
    const int arow    = lane & 15;                        // A-side geometry
    const int ahalf   = (lane >> 4) & 1;

    // staging coords for this thread (4 chunks of 16B per buffer per tile)
    int srow[4], sck[4]; uint32_t soff[4];
    #pragma unroll
    for (int i = 0; i < 4; i++) {
        int c = tid + i * 256;              // 0..1023
        srow[i] = c >> 3; sck[i] = c & 7;
        soff[i] = (uint32_t)(srow[i] * 128 + ((sck[i] ^ (srow[i] & 7)) << 4));
    }

    auto issue_stage = [&](int k0, int buf) {
        const uint32_t base = sb + buf * PG_STAGE;
        #pragma unroll
        for (int i = 0; i < 4; i++) {
            int asrc = (m0 + srow[i]) * (DD/8) + k0/8 + sck[i];
            cpasync16(base + PG_AH + soff[i], Ahi + asrc);
            cpasync16(base + PG_AL + soff[i], Alo + asrc);
            int bsrc = (n0 + srow[i]) * (DD/8) + k0/8 + sck[i];
            cpasync16(base + PG_BH + soff[i], Bhi + bsrc);
            cpasync16(base + PG_BL + soff[i], Blo + bsrc);
        }
    };

    float acc[16][4];
    #pragma unroll
    for (int j = 0; j < 16; j++)
        #pragma unroll
        for (int c = 0; c < 4; c++) acc[j][c] = 0.0f;

    // prologue: prefetch tile 0
    issue_stage(0, 0);
    CP_COMMIT();

    for (int t = 0; t < 16; t++) {
        if (t < 15) {
            issue_stage((t + 1) * 64, (t + 1) & 1);
            CP_COMMIT();
            CP_WAIT(1);                 // tile t landed; t+1 in flight
        } else {
            CP_WAIT(0);
        }
        __syncthreads();

        const uint32_t base = sb + (t & 1) * PG_STAGE;
        #pragma unroll
        for (int ks = 0; ks < 4; ks++) {
            int ar = w * 16 + arow;
            int ac = ks * 2 + ahalf;
            uint32_t aoff = (uint32_t)(ar * 128 + ((ac ^ (ar & 7)) << 4));
            uint32_t ah4[4], al4[4];
            ldsm4(ah4, base + PG_AH + aoff);
            ldsm4(al4, base + PG_AL + aoff);

            #pragma unroll
            for (int jp = 0; jp < 8; jp++) {
                int br = jp * 16 + row_off;
                int bc = ks * 2 + khalf;
                uint32_t boff = (uint32_t)(br * 128 + ((bc ^ (br & 7)) << 4));
                uint32_t bh4[4], bl4[4];
                ldsm4(bh4, base + PG_BH + boff);
                ldsm4(bl4, base + PG_BL + boff);
                mma16816(acc[2*jp],   ah4, bh4);
                mma16816(acc[2*jp],   al4, bh4);
                mma16816(acc[2*jp],   ah4, bl4);
                mma16816(acc[2*jp+1], ah4, bh4 + 2);
                mma16816(acc[2*jp+1], al4, bh4 + 2);
                mma16816(acc[2*jp+1], ah4, bl4 + 2);
            }
        }
        __syncthreads();   // all reads of buf (t&1) done before t+1 issues into it
    }

    // epilogue: add bias, scatter to [b][h][s][d]
    const int r0  = m0 + w * 16 + (lane >> 2);
    const int cq  = (lane & 3) * 2;
    const int b0  = r0 >> 11,      s0 = r0 & (SS - 1);
    const int b1  = (r0+8) >> 11,  s1 = (r0+8) & (SS - 1);
    #pragma unroll
    for (int j = 0; j < 16; j++) {
        int n = n0 + j * 8 + cq;
        int h = n >> 6, d = n & (DH - 1);
        float2 w0 = make_float2(acc[j][0] + bias[n], acc[j][1] + bias[n+1]);
        float2 w1 = make_float2(acc[j][2] + bias[n], acc[j][3] + bias[n+1]);
        *(float2*)&dst[(((size_t)b0 * HH + h) * SS + s0) * DH + d] = w0;
        *(float2*)&dst[(((size_t)b1 * HH + h) * SS + s1) * DH + d] = w1;
    }
}

// ---------------------------------------------------------------------------
// Pointwise fused K -> bf16 hi/lo split (natural layout). 8 elems/thread.
// ---------------------------------------------------------------------------
__global__ __launch_bounds__(128) void split_k()
{
    const int i8 = blockIdx.x * 128 + threadIdx.x;
    const float4* Q = (const float4*)g_Q;
    const float4* K = (const float4*)g_K;
    float4 qa = Q[i8*2], qb = Q[i8*2+1];
    float4 ka = K[i8*2], kb = K[i8*2+1];
    float f[8] = {
        logsig(logsig(qa.x)+qa.x+ka.x), logsig(logsig(qa.y)+qa.y+ka.y),
        logsig(logsig(qa.z)+qa.z+ka.z), logsig(logsig(qa.w)+qa.w+ka.w),
        logsig(logsig(qb.x)+qb.x+kb.x), logsig(logsig(qb.y)+qb.y+kb.y),
        logsig(logsig(qb.z)+qb.z+kb.z), logsig(logsig(qb.w)+qb.w+kb.w) };
    __nv_bfloat16 hi[8], lo[8];
    #pragma unroll
    for (int j = 0; j < 8; j++) {
        hi[j] = __float2bfloat16(f[j]);
        lo[j] = __float2bfloat16(f[j] - __bfloat162float(hi[j]));
    }
    ((uint4*)g_Khi)[i8] = *(const uint4*)hi;
    ((uint4*)g_Klo)[i8] = *(const uint4*)lo;
}

// ---------------------------------------------------------------------------
// V(=Q) transpose to [bh][d][s] with bf16 hi/lo split. 64x64 tiles, 256 thr.
// ---------------------------------------------------------------------------
__global__ __launch_bounds__(256) void transpose_v()
{
    __shared__ float tq[64][65];
    const int bh = blockIdx.y;
    const int s0 = blockIdx.x * 64;
    const int tid = threadIdx.x;

    const float4* Qsrc = (const float4*)(g_Q + (size_t)bh*SS*DH + (size_t)s0*DH);
    #pragma unroll
    for (int i = 0; i < 4; i++) {
        int idx4 = tid + i * 256;
        int row  = idx4 >> 4;
        int c    = (idx4 & 15) * 4;
        float4 q = Qsrc[idx4];
        tq[row][c+0] = q.x; tq[row][c+1] = q.y; tq[row][c+2] = q.z; tq[row][c+3] = q.w;
    }
    __syncthreads();

    const int d  = tid >> 2;
    const int sq = (tid & 3) * 16;
    __nv_bfloat16 hi[16], lo[16];
    #pragma unroll
    for (int c = 0; c < 16; c++) {
        float v = tq[sq+c][d];
        hi[c] = __float2bfloat16(v);
        lo[c] = __float2bfloat16(v - __bfloat162float(hi[c]));
    }
    size_t off = (size_t)bh*DH*SS + (size_t)d*SS + s0 + sq;
    *(uint4*)(g_Vhi + off)     = *(const uint4*)hi;
    *(uint4*)(g_Vhi + off + 8) = *(const uint4*)(hi + 8);
    *(uint4*)(g_Vlo + off)     = *(const uint4*)lo;
    *(uint4*)(g_Vlo + off + 8) = *(const uint4*)(lo + 8);
}

// ---------------------------------------------------------------------------
// mma.sync flash attention (unchanged — known good).
// ---------------------------------------------------------------------------
#define SM_KH 0
#define SM_KL 16384
#define SM_VH 32768
#define SM_VL 49152
#define ATTN_SMEM 65536

__global__ __launch_bounds__(256, 1) void attn(
    const int* __restrict__ mask, float* __restrict__ out)
{
    extern __shared__ char smem[];
    const uint32_t sb = smem_u32(smem);
    const int tid  = threadIdx.x;
    const int w    = tid >> 5;
    const int lane = tid & 31;
    const int bh = blockIdx.y;
    const int b  = bh >> 4;
    const int h  = bh & (HH - 1);
    const int q0 = blockIdx.x * 128;

    const int row_off = (lane & 7) + ((lane & 16) >> 1);
    const int khalf   = (lane >> 3) & 1;

    {
        float* Qs = (float*)smem;
        const float* src = g_Q + ((size_t)bh * SS + q0) * DH;
        #pragma unroll
        for (int i = 0; i < 8; i++) {
            int idx4 = tid + i * 256;
            ((float4*)Qs)[idx4] = ((const float4*)src)[idx4];
        }
        __syncthreads();
    }

    const int r0 = lane >> 2;
    const int cq = (lane & 3) * 2;
    uint32_t qh[4][4], ql[4][4];
    {
        const float* Qs = (const float*)smem;
        const int m0 = w * 16 + r0;
        #pragma unroll
        for (int ks = 0; ks < 4; ks++) {
            int c0 = ks * 16 + cq;
            float x0 = Qs[m0*64 + c0]     * -0.125f, y0 = Qs[m0*64 + c0 + 1]     * -0.125f;
            float x1 = Qs[(m0+8)*64 + c0] * -0.125f, y1 = Qs[(m0+8)*64 + c0 + 1] * -0.125f;
            float x2 = Qs[m0*64 + c0 + 8] * -0.125f, y2 = Qs[m0*64 + c0 + 9]     * -0.125f;
            float x3 = Qs[(m0+8)*64 + c0 + 8] * -0.125f, y3 = Qs[(m0+8)*64 + c0 + 9] * -0.125f;
            split_pair(x0, y0, qh[ks][0], ql[ks][0]);
            split_pair(x1, y1, qh[ks][1], ql[ks][1]);
            split_pair(x2, y2, qh[ks][2], ql[ks][2]);
            split_pair(x3, y3, qh[ks][3], ql[ks][3]);
        }
    }

    const bool mq0 = (mask[b * SS + q0 + w*16 + r0]     == 0);
    const bool mq1 = (mask[b * SS + q0 + w*16 + r0 + 8] == 0);

    float l0 = 0.0f, l1 = 0.0f;
    float oacc[8][4];
    #pragma unroll
    for (int j = 0; j < 8; j++)
        #pragma unroll
        for (int c = 0; c < 4; c++) oacc[j][c] = 0.0f;

    const uint4* Khi = (const uint4*)(g_Khi + (size_t)bh * SS * DH);
    const uint4* Klo = (const uint4*)(g_Klo + (size_t)bh * SS * DH);
    const uint4* Vhi = (const uint4*)(g_Vhi + (size_t)bh * DH * SS);
    const uint4* Vlo = (const uint4*)(g_Vlo + (size_t)bh * DH * SS);

    for (int t = 0; t < 16; t++) {
        const int t0 = t * 128;
        __syncthreads();

        #pragma unroll
        for (int i = 0; i < 4; i++) {
            int c = tid + i * 256;
            int rk = c >> 3, ck = c & 7;
            uint32_t kd = (uint32_t)(rk * 128 + ((ck ^ (rk & 7)) << 4));
            int ksrc = (t0 + rk) * 8 + ck;
            *(uint4*)(smem + SM_KH + kd) = Khi[ksrc];
            *(uint4*)(smem + SM_KL + kd) = Klo[ksrc];
            int rv = c >> 4, cv = c & 15;
            uint32_t vd = (uint32_t)(rv * 256 + ((cv ^ (rv & 7)) << 4));
            int vsrc = rv * (SS/8) + t0/8 + cv;
            *(uint4*)(smem + SM_VH + vd) = Vhi[vsrc];
            *(uint4*)(smem + SM_VL + vd) = Vlo[vsrc];
        }
        __syncthreads();

        float sacc[16][4];
        #pragma unroll
        for (int j = 0; j < 16; j++)
            #pragma unroll
            for (int c = 0; c < 4; c++) sacc[j][c] = 0.0f;

        #pragma unroll
        for (int ks = 0; ks < 4; ks++) {
            #pragma unroll
            for (int jp = 0; jp < 8; jp++) {
                int row = jp * 16 + row_off;
                int chunk = ks * 2 + khalf;
                uint32_t off = (uint32_t)(row * 128 + ((chunk ^ (row & 7)) << 4));
                uint32_t bh4[4], bl4[4];
                ldsm4(bh4, sb + SM_KH + off);
                ldsm4(bl4, sb + SM_KL + off);
                mma16816(sacc[2*jp],   qh[ks], bh4);
                mma16816(sacc[2*jp],   ql[ks], bh4);
                mma16816(sacc[2*jp],   qh[ks], bl4);
                mma16816(sacc[2*jp+1], qh[ks], bh4 + 2);
                mma16816(sacc[2*jp+1], ql[ks], bh4 + 2);
                mma16816(sacc[2*jp+1], qh[ks], bl4 + 2);
            }
        }

        uint32_t phi[8][4], plo[8][4];
        #pragma unroll
        for (int kp = 0; kp < 8; kp++) {
            float p[8];
            #pragma unroll
            for (int half = 0; half < 2; half++) {
                const float* sc = sacc[2*kp + half];
                p[half*4+0] = __expf(mq0 ? 0.0f : sc[0]);
                p[half*4+1] = __expf(mq0 ? 0.0f : sc[1]);
                p[half*4+2] = __expf(mq1 ? 0.0f : sc[2]);
                p[half*4+3] = __expf(mq1 ? 0.0f : sc[3]);
            }
            l0 += p[0] + p[1] + p[4] + p[5];
            l1 += p[2] + p[3] + p[6] + p[7];
            split_pair(p[0], p[1], phi[kp][0], plo[kp][0]);
            split_pair(p[2], p[3], phi[kp][1], plo[kp][1]);
            split_pair(p[4], p[5], phi[kp][2], plo[kp][2]);
            split_pair(p[6], p[7], phi[kp][3], plo[kp][3]);
        }

        #pragma unroll
        for (int kp = 0; kp < 8; kp++) {
            #pragma unroll
            for (int jp = 0; jp < 4; jp++) {
                int row = jp * 16 + row_off;
                int chunk = kp * 2 + khalf;
                uint32_t off = (uint32_t)(row * 256 + ((chunk ^ (row & 7)) << 4));
                uint32_t vh4[4], vl4[4];
                ldsm4(vh4, sb + SM_VH + off);
                ldsm4(vl4, sb + SM_VL + off);
                mma16816(oacc[2*jp],   phi[kp], vh4);
                mma16816(oacc[2*jp],   plo[kp], vh4);
                mma16816(oacc[2*jp],   phi[kp], vl4);
                mma16816(oacc[2*jp+1], phi[kp], vh4 + 2);
                mma16816(oacc[2*jp+1], plo[kp], vh4 + 2);
                mma16816(oacc[2*jp+1], phi[kp], vl4 + 2);
            }
        }
    }

    l0 += __shfl_xor_sync(0xffffffffu, l0, 1);
    l0 += __shfl_xor_sync(0xffffffffu, l0, 2);
    l1 += __shfl_xor_sync(0xffffffffu, l1, 1);
    l1 += __shfl_xor_sync(0xffffffffu, l1, 2);
    const float inv0 = 1.0f / l0;
    const float inv1 = 1.0f / l1;

    const int s0 = q0 + w*16 + r0;
    float* o0 = out + ((size_t)b * SS + s0)     * (HH*DH) + h * DH;
    float* o1 = out + ((size_t)b * SS + s0 + 8) * (HH*DH) + h * DH;
    #pragma unroll
    for (int j = 0; j < 8; j++) {
        int col = j * 8 + cq;
        float2 w0 = make_float2(oacc[j][0] * inv0, oacc[j][1] * inv0);
        float2 w1 = make_float2(oacc[j][2] * inv1, oacc[j][3] * inv1);
        *(float2*)(o0 + col) = w0;
        *(float2*)(o1 + col) = w1;
    }
}

// ---------------------------------------------------------------------------
extern "C" void kernel_launch(void* const* d_in, const int* in_sizes, int n_in,
                              void* d_out, int out_size)
{
    const float* hs   = (const float*)d_in[0];
    const int*   mask = (const int*)  d_in[1];
    const float* Wq   = (const float*)d_in[2];
    const float* bq   = (const float*)d_in[3];
    const float* Wk   = (const float*)d_in[4];
    const float* bk   = (const float*)d_in[5];
    float* out = (float*)d_out;

    split_hs<<<(MROWS*DD) / (256 * 8), 256>>>(hs);          // 2048 blocks
    dim3 wgrid(DD / 64, DD / 64, 2);                        // (16,16,2)
    split_w<<<wgrid, 256>>>(Wq, Wk);

    cudaFuncSetAttribute(proj_gemm, cudaFuncAttributeMaxDynamicSharedMemorySize, PG_SMEM);
    dim3 pgrid(DD / 128, MROWS / 128, 2);                   // (8,32,2)
    proj_gemm<<<pgrid, 256, PG_SMEM>>>(bq, bk);

    split_k<<<(BB*HH*SS*DH) / (128 * 8), 128>>>();
    dim3 tgrid(SS / 64, BB * HH);
    transpose_v<<<tgrid, 256>>>();

    cudaFuncSetAttribute(attn, cudaFuncAttributeMaxDynamicSharedMemorySize, ATTN_SMEM);
    dim3 agrid(SS / 128, BB * HH);                          // (16,32)
    attn<<<agrid, 256, ATTN_SMEM>>>(mask, out);
}

// round 11
// speedup vs baseline: 1.7966x; 1.0914x over previous
#include <cuda_runtime.h>
#include <cuda_bf16.h>
#include <math.h>
#include <cstdint>

#define BB 2
#define SS 2048
#define DD 1024
#define HH 16
#define DH 64
#define MROWS (BB*SS)   // 4096

// fp32 scratch (projection outputs)
__device__ float g_Q[BB*HH*SS*DH];    // Q natural [bh][s][d] (also the values)
__device__ float g_K[BB*HH*SS*DH];    // K raw     [bh][s][d]
// bf16 split operands for attention
__device__ __nv_bfloat16 g_Khi[BB*HH*SS*DH];  // fused K, natural [bh][s][d]
__device__ __nv_bfloat16 g_Klo[BB*HH*SS*DH];
__device__ __nv_bfloat16 g_Vhi[BB*HH*DH*SS];  // V(=Q) transposed [bh][d][s]
__device__ __nv_bfloat16 g_Vlo[BB*HH*DH*SS];
// bf16 split operands for projections
__device__ __nv_bfloat16 g_Ahi[MROWS*DD];     // hidden_states [m][k]
__device__ __nv_bfloat16 g_Alo[MROWS*DD];
__device__ __nv_bfloat16 g_Wthi[2*DD*DD];     // W transposed [w][n][k]
__device__ __nv_bfloat16 g_Wtlo[2*DD*DD];

__device__ __forceinline__ float logsig(float x) {
    return fminf(x, 0.0f) - log1pf(expf(-fabsf(x)));
}

// ---- mma.sync / ldmatrix / cp.async helpers (sm_80+ PTX) ------------------
__device__ __forceinline__ uint32_t smem_u32(const void* p) {
    uint32_t a;
    asm("{ .reg .u64 t; cvta.to.shared.u64 t, %1; cvt.u32.u64 %0, t; }" : "=r"(a) : "l"(p));
    return a;
}
__device__ __forceinline__ void ldsm4(uint32_t* r, uint32_t addr) {
    asm volatile("ldmatrix.sync.aligned.m8n8.x4.shared.b16 {%0,%1,%2,%3}, [%4];"
        : "=r"(r[0]), "=r"(r[1]), "=r"(r[2]), "=r"(r[3]) : "r"(addr));
}
__device__ __forceinline__ void mma16816(float* c, const uint32_t* a, const uint32_t* b) {
    asm volatile(
        "mma.sync.aligned.m16n8k16.row.col.f32.bf16.bf16.f32 "
        "{%0,%1,%2,%3}, {%4,%5,%6,%7}, {%8,%9}, {%0,%1,%2,%3};"
        : "+f"(c[0]), "+f"(c[1]), "+f"(c[2]), "+f"(c[3])
        : "r"(a[0]), "r"(a[1]), "r"(a[2]), "r"(a[3]), "r"(b[0]), "r"(b[1]));
}
__device__ __forceinline__ void split_pair(float x, float y, uint32_t& hi, uint32_t& lo) {
    __nv_bfloat16 hx = __float2bfloat16(x), hy = __float2bfloat16(y);
    __nv_bfloat16 lx = __float2bfloat16(x - __bfloat162float(hx));
    __nv_bfloat16 ly = __float2bfloat16(y - __bfloat162float(hy));
    __nv_bfloat162 hv; hv.x = hx; hv.y = hy;
    __nv_bfloat162 lv; lv.x = lx; lv.y = ly;
    hi = *(const uint32_t*)&hv;
    lo = *(const uint32_t*)&lv;
}
__device__ __forceinline__ void cpasync16(uint32_t saddr, const void* g) {
    asm volatile("cp.async.cg.shared.global [%0], [%1], 16;" :: "r"(saddr), "l"(g));
}
#define CP_COMMIT()     asm volatile("cp.async.commit_group;" ::: "memory")
#define CP_WAIT(n)      asm volatile("cp.async.wait_group %0;" :: "n"(n) : "memory")

// ---------------------------------------------------------------------------
// split_hs: hidden_states fp32 [m][k] -> bf16 hi/lo. 8 elems/thread.
// ---------------------------------------------------------------------------
__global__ __launch_bounds__(256) void split_hs(const float* __restrict__ hs)
{
    const int i8 = blockIdx.x * 256 + threadIdx.x;
    float4 a = ((const float4*)hs)[i8*2];
    float4 b = ((const float4*)hs)[i8*2+1];
    float f[8] = { a.x,a.y,a.z,a.w, b.x,b.y,b.z,b.w };
    __nv_bfloat16 hi[8], lo[8];
    #pragma unroll
    for (int j = 0; j < 8; j++) {
        hi[j] = __float2bfloat16(f[j]);
        lo[j] = __float2bfloat16(f[j] - __bfloat162float(hi[j]));
    }
    ((uint4*)g_Ahi)[i8] = *(const uint4*)hi;
    ((uint4*)g_Alo)[i8] = *(const uint4*)lo;
}

// ---------------------------------------------------------------------------
// split_w: W fp32 [k][n] -> Wt bf16 hi/lo [n][k]. 64x64 tiles, 256 threads.
// ---------------------------------------------------------------------------
__global__ __launch_bounds__(256) void split_w(
    const float* __restrict__ Wq, const float* __restrict__ Wk)
{
    __shared__ float tw[64][65];
    const int wsel = blockIdx.z;
    const float* W = wsel ? Wk : Wq;
    const int k0 = blockIdx.y * 64;
    const int n0 = blockIdx.x * 64;
    const int tid = threadIdx.x;

    #pragma unroll
    for (int i = 0; i < 4; i++) {
        int idx4 = tid + i * 256;        // 0..1023
        int row  = idx4 >> 4;            // k within tile
        int c    = (idx4 & 15) * 4;      // n
        float4 v = *(const float4*)&W[(size_t)(k0 + row) * DD + n0 + c];
        tw[row][c+0] = v.x; tw[row][c+1] = v.y; tw[row][c+2] = v.z; tw[row][c+3] = v.w;
    }
    __syncthreads();

    const int n  = tid >> 2;             // 0..63
    const int kq = (tid & 3) * 16;
    __nv_bfloat16 hi[16], lo[16];
    #pragma unroll
    for (int c = 0; c < 16; c++) {
        float v = tw[kq+c][n];
        hi[c] = __float2bfloat16(v);
        lo[c] = __float2bfloat16(v - __bfloat162float(hi[c]));
    }
    size_t off = (size_t)wsel*DD*DD + (size_t)(n0 + n)*DD + k0 + kq;
    *(uint4*)(g_Wthi + off)     = *(const uint4*)hi;
    *(uint4*)(g_Wthi + off + 8) = *(const uint4*)(hi + 8);
    *(uint4*)(g_Wtlo + off)     = *(const uint4*)lo;
    *(uint4*)(g_Wtlo + off + 8) = *(const uint4*)(lo + 8);
}

// ---------------------------------------------------------------------------
// Projection GEMM on tensor pipe, 2-stage cp.async pipeline. (R9 — known good)
// ---------------------------------------------------------------------------
#define PG_AH 0
#define PG_AL 16384
#define PG_BH 32768
#define PG_BL 49152
#define PG_STAGE 65536
#define PG_SMEM (2*PG_STAGE)

__global__ __launch_bounds__(256) void proj_gemm(
    const float* __restrict__ bq, const float* __restrict__ bk)
{
    extern __shared__ char smem[];
    const uint32_t sb = smem_u32(smem);
    const int tid  = threadIdx.x;
    const int w    = tid >> 5;
    const int lane = tid & 31;
    const int wsel = blockIdx.z;
    const int m0 = blockIdx.y * 128;
    const int n0 = blockIdx.x * 128;

    const float* bias = wsel ? bk : bq;
    float* dst = wsel ? g_K : g_Q;
    const uint4* Ahi = (const uint4*)g_Ahi;
    const uint4* Alo = (const uint4*)g_Alo;
    const uint4* Bhi = (const uint4*)(g_Wthi + (size_t)wsel * DD * DD);
    const uint4* Blo = (const uint4*)(g_Wtlo + (size_t)wsel * DD * DD);

    const int row_off = (lane & 7) + ((lane & 16) >> 1);
    const int khalf   = (lane >> 3) & 1;
    const int arow    = lane & 15;
    const int ahalf   = (lane >> 4) & 1;

    int srow[4], sck[4]; uint32_t soff[4];
    #pragma unroll
    for (int i = 0; i < 4; i++) {
        int c = tid + i * 256;
        srow[i] = c >> 3; sck[i] = c & 7;
        soff[i] = (uint32_t)(srow[i] * 128 + ((sck[i] ^ (srow[i] & 7)) << 4));
    }

    auto issue_stage = [&](int k0, int buf) {
        const uint32_t base = sb + buf * PG_STAGE;
        #pragma unroll
        for (int i = 0; i < 4; i++) {
            int asrc = (m0 + srow[i]) * (DD/8) + k0/8 + sck[i];
            cpasync16(base + PG_AH + soff[i], Ahi + asrc);
            cpasync16(base + PG_AL + soff[i], Alo + asrc);
            int bsrc = (n0 + srow[i]) * (DD/8) + k0/8 + sck[i];
            cpasync16(base + PG_BH + soff[i], Bhi + bsrc);
            cpasync16(base + PG_BL + soff[i], Blo + bsrc);
        }
    };

    float acc[16][4];
    #pragma unroll
    for (int j = 0; j < 16; j++)
        #pragma unroll
        for (int c = 0; c < 4; c++) acc[j][c] = 0.0f;

    issue_stage(0, 0);
    CP_COMMIT();

    for (int t = 0; t < 16; t++) {
        if (t < 15) {
            issue_stage((t + 1) * 64, (t + 1) & 1);
            CP_COMMIT();
            CP_WAIT(1);
        } else {
            CP_WAIT(0);
        }
        __syncthreads();

        const uint32_t base = sb + (t & 1) * PG_STAGE;
        #pragma unroll
        for (int ks = 0; ks < 4; ks++) {
            int ar = w * 16 + arow;
            int ac = ks * 2 + ahalf;
            uint32_t aoff = (uint32_t)(ar * 128 + ((ac ^ (ar & 7)) << 4));
            uint32_t ah4[4], al4[4];
            ldsm4(ah4, base + PG_AH + aoff);
            ldsm4(al4, base + PG_AL + aoff);

            #pragma unroll
            for (int jp = 0; jp < 8; jp++) {
                int br = jp * 16 + row_off;
                int bc = ks * 2 + khalf;
                uint32_t boff = (uint32_t)(br * 128 + ((bc ^ (br & 7)) << 4));
                uint32_t bh4[4], bl4[4];
                ldsm4(bh4, base + PG_BH + boff);
                ldsm4(bl4, base + PG_BL + boff);
                mma16816(acc[2*jp],   ah4, bh4);
                mma16816(acc[2*jp],   al4, bh4);
                mma16816(acc[2*jp],   ah4, bl4);
                mma16816(acc[2*jp+1], ah4, bh4 + 2);
                mma16816(acc[2*jp+1], al4, bh4 + 2);
                mma16816(acc[2*jp+1], ah4, bl4 + 2);
            }
        }
        __syncthreads();
    }

    const int r0  = m0 + w * 16 + (lane >> 2);
    const int cq  = (lane & 3) * 2;
    const int b0  = r0 >> 11,      s0 = r0 & (SS - 1);
    const int b1  = (r0+8) >> 11,  s1 = (r0+8) & (SS - 1);
    #pragma unroll
    for (int j = 0; j < 16; j++) {
        int n = n0 + j * 8 + cq;
        int h = n >> 6, d = n & (DH - 1);
        float2 w0 = make_float2(acc[j][0] + bias[n], acc[j][1] + bias[n+1]);
        float2 w1 = make_float2(acc[j][2] + bias[n], acc[j][3] + bias[n+1]);
        *(float2*)&dst[(((size_t)b0 * HH + h) * SS + s0) * DH + d] = w0;
        *(float2*)&dst[(((size_t)b1 * HH + h) * SS + s1) * DH + d] = w1;
    }
}

// ---------------------------------------------------------------------------
// Pointwise fused K -> bf16 hi/lo split (natural layout). 8 elems/thread.
// ---------------------------------------------------------------------------
__global__ __launch_bounds__(128) void split_k()
{
    const int i8 = blockIdx.x * 128 + threadIdx.x;
    const float4* Q = (const float4*)g_Q;
    const float4* K = (const float4*)g_K;
    float4 qa = Q[i8*2], qb = Q[i8*2+1];
    float4 ka = K[i8*2], kb = K[i8*2+1];
    float f[8] = {
        logsig(logsig(qa.x)+qa.x+ka.x), logsig(logsig(qa.y)+qa.y+ka.y),
        logsig(logsig(qa.z)+qa.z+ka.z), logsig(logsig(qa.w)+qa.w+ka.w),
        logsig(logsig(qb.x)+qb.x+kb.x), logsig(logsig(qb.y)+qb.y+kb.y),
        logsig(logsig(qb.z)+qb.z+kb.z), logsig(logsig(qb.w)+qb.w+kb.w) };
    __nv_bfloat16 hi[8], lo[8];
    #pragma unroll
    for (int j = 0; j < 8; j++) {
        hi[j] = __float2bfloat16(f[j]);
        lo[j] = __float2bfloat16(f[j] - __bfloat162float(hi[j]));
    }
    ((uint4*)g_Khi)[i8] = *(const uint4*)hi;
    ((uint4*)g_Klo)[i8] = *(const uint4*)lo;
}

// ---------------------------------------------------------------------------
// V(=Q) transpose to [bh][d][s] with bf16 hi/lo split. 64x64 tiles, 256 thr.
// ---------------------------------------------------------------------------
__global__ __launch_bounds__(256) void transpose_v()
{
    __shared__ float tq[64][65];
    const int bh = blockIdx.y;
    const int s0 = blockIdx.x * 64;
    const int tid = threadIdx.x;

    const float4* Qsrc = (const float4*)(g_Q + (size_t)bh*SS*DH + (size_t)s0*DH);
    #pragma unroll
    for (int i = 0; i < 4; i++) {
        int idx4 = tid + i * 256;
        int row  = idx4 >> 4;
        int c    = (idx4 & 15) * 4;
        float4 q = Qsrc[idx4];
        tq[row][c+0] = q.x; tq[row][c+1] = q.y; tq[row][c+2] = q.z; tq[row][c+3] = q.w;
    }
    __syncthreads();

    const int d  = tid >> 2;
    const int sq = (tid & 3) * 16;
    __nv_bfloat16 hi[16], lo[16];
    #pragma unroll
    for (int c = 0; c < 16; c++) {
        float v = tq[sq+c][d];
        hi[c] = __float2bfloat16(v);
        lo[c] = __float2bfloat16(v - __bfloat162float(hi[c]));
    }
    size_t off = (size_t)bh*DH*SS + (size_t)d*SS + s0 + sq;
    *(uint4*)(g_Vhi + off)     = *(const uint4*)hi;
    *(uint4*)(g_Vhi + off + 8) = *(const uint4*)(hi + 8);
    *(uint4*)(g_Vlo + off)     = *(const uint4*)lo;
    *(uint4*)(g_Vlo + off + 8) = *(const uint4*)(lo + 8);
}

// ---------------------------------------------------------------------------
// mma.sync flash attention with 2-stage cp.async pipeline.
// smem: 2 stages x (KH | KL | VH | VL), each 16KB -> 128KB dynamic.
// Q stages through the stage-1 buffer (fp32 scratch) during tile-0 prefetch.
// ---------------------------------------------------------------------------
#define AT_KH 0
#define AT_KL 16384
#define AT_VH 32768
#define AT_VL 49152
#define AT_STAGE 65536
#define ATTN_SMEM (2*AT_STAGE)

__global__ __launch_bounds__(256, 1) void attn(
    const int* __restrict__ mask, float* __restrict__ out)
{
    extern __shared__ char smem[];
    const uint32_t sb = smem_u32(smem);
    const int tid  = threadIdx.x;
    const int w    = tid >> 5;
    const int lane = tid & 31;
    const int bh = blockIdx.y;
    const int b  = bh >> 4;
    const int h  = bh & (HH - 1);
    const int q0 = blockIdx.x * 128;

    const int row_off = (lane & 7) + ((lane & 16) >> 1);
    const int khalf   = (lane >> 3) & 1;

    const uint4* Khi = (const uint4*)(g_Khi + (size_t)bh * SS * DH);
    const uint4* Klo = (const uint4*)(g_Klo + (size_t)bh * SS * DH);
    const uint4* Vhi = (const uint4*)(g_Vhi + (size_t)bh * DH * SS);
    const uint4* Vlo = (const uint4*)(g_Vlo + (size_t)bh * DH * SS);

    // staging coords (4 chunks/thread for K, 4 for V)
    int krow[4], kck[4]; uint32_t koff[4];
    int vrow[4], vck[4]; uint32_t voff[4];
    #pragma unroll
    for (int i = 0; i < 4; i++) {
        int c = tid + i * 256;              // 0..1023
        krow[i] = c >> 3; kck[i] = c & 7;
        koff[i] = (uint32_t)(krow[i] * 128 + ((kck[i] ^ (krow[i] & 7)) << 4));
        vrow[i] = c >> 4; vck[i] = c & 15;
        voff[i] = (uint32_t)(vrow[i] * 256 + ((vck[i] ^ (vrow[i] & 7)) << 4));
    }

    auto issue_stage = [&](int t0, int buf) {
        const uint32_t base = sb + buf * AT_STAGE;
        #pragma unroll
        for (int i = 0; i < 4; i++) {
            int ksrc = (t0 + krow[i]) * 8 + kck[i];
            cpasync16(base + AT_KH + koff[i], Khi + ksrc);
            cpasync16(base + AT_KL + koff[i], Klo + ksrc);
            int vsrc = vrow[i] * (SS/8) + t0/8 + vck[i];
            cpasync16(base + AT_VH + voff[i], Vhi + vsrc);
            cpasync16(base + AT_VL + voff[i], Vlo + vsrc);
        }
    };

    // prologue: prefetch tile 0 into buf0, stage Q through buf1 scratch
    issue_stage(0, 0);
    CP_COMMIT();

    {
        float* Qs = (float*)(smem + AT_STAGE);     // 32KB fp32 scratch in buf1
        const float* src = g_Q + ((size_t)bh * SS + q0) * DH;
        #pragma unroll
        for (int i = 0; i < 8; i++) {
            int idx4 = tid + i * 256;
            ((float4*)Qs)[idx4] = ((const float4*)src)[idx4];
        }
        __syncthreads();
    }

    const int r0 = lane >> 2;
    const int cq = (lane & 3) * 2;
    uint32_t qh[4][4], ql[4][4];
    {
        const float* Qs = (const float*)(smem + AT_STAGE);
        const int m0 = w * 16 + r0;
        #pragma unroll
        for (int ks = 0; ks < 4; ks++) {
            int c0 = ks * 16 + cq;
            float x0 = Qs[m0*64 + c0]     * -0.125f, y0 = Qs[m0*64 + c0 + 1]     * -0.125f;
            float x1 = Qs[(m0+8)*64 + c0] * -0.125f, y1 = Qs[(m0+8)*64 + c0 + 1] * -0.125f;
            float x2 = Qs[m0*64 + c0 + 8] * -0.125f, y2 = Qs[m0*64 + c0 + 9]     * -0.125f;
            float x3 = Qs[(m0+8)*64 + c0 + 8] * -0.125f, y3 = Qs[(m0+8)*64 + c0 + 9] * -0.125f;
            split_pair(x0, y0, qh[ks][0], ql[ks][0]);
            split_pair(x1, y1, qh[ks][1], ql[ks][1]);
            split_pair(x2, y2, qh[ks][2], ql[ks][2]);
            split_pair(x3, y3, qh[ks][3], ql[ks][3]);
        }
        __syncthreads();   // buf1 scratch reads done before tile-1 prefetch targets it
    }

    const bool mq0 = (mask[b * SS + q0 + w*16 + r0]     == 0);
    const bool mq1 = (mask[b * SS + q0 + w*16 + r0 + 8] == 0);

    float l0 = 0.0f, l1 = 0.0f;
    float oacc[8][4];
    #pragma unroll
    for (int j = 0; j < 8; j++)
        #pragma unroll
        for (int c = 0; c < 4; c++) oacc[j][c] = 0.0f;

    for (int t = 0; t < 16; t++) {
        if (t < 15) {
            issue_stage((t + 1) * 128, (t + 1) & 1);
            CP_COMMIT();
            CP_WAIT(1);                 // tile t landed; t+1 in flight
        } else {
            CP_WAIT(0);
        }
        __syncthreads();

        const uint32_t base = sb + (t & 1) * AT_STAGE;

        float sacc[16][4];
        #pragma unroll
        for (int j = 0; j < 16; j++)
            #pragma unroll
            for (int c = 0; c < 4; c++) sacc[j][c] = 0.0f;

        #pragma unroll
        for (int ks = 0; ks < 4; ks++) {
            #pragma unroll
            for (int jp = 0; jp < 8; jp++) {
                int row = jp * 16 + row_off;
                int chunk = ks * 2 + khalf;
                uint32_t off = (uint32_t)(row * 128 + ((chunk ^ (row & 7)) << 4));
                uint32_t bh4[4], bl4[4];
                ldsm4(bh4, base + AT_KH + off);
                ldsm4(bl4, base + AT_KL + off);
                mma16816(sacc[2*jp],   qh[ks], bh4);
                mma16816(sacc[2*jp],   ql[ks], bh4);
                mma16816(sacc[2*jp],   qh[ks], bl4);
                mma16816(sacc[2*jp+1], qh[ks], bh4 + 2);
                mma16816(sacc[2*jp+1], ql[ks], bh4 + 2);
                mma16816(sacc[2*jp+1], qh[ks], bl4 + 2);
            }
        }

        uint32_t phi[8][4], plo[8][4];
        #pragma unroll
        for (int kp = 0; kp < 8; kp++) {
            float p[8];
            #pragma unroll
            for (int half = 0; half < 2; half++) {
                const float* sc = sacc[2*kp + half];
                p[half*4+0] = __expf(mq0 ? 0.0f : sc[0]);
                p[half*4+1] = __expf(mq0 ? 0.0f : sc[1]);
                p[half*4+2] = __expf(mq1 ? 0.0f : sc[2]);
                p[half*4+3] = __expf(mq1 ? 0.0f : sc[3]);
            }
            l0 += p[0] + p[1] + p[4] + p[5];
            l1 += p[2] + p[3] + p[6] + p[7];
            split_pair(p[0], p[1], phi[kp][0], plo[kp][0]);
            split_pair(p[2], p[3], phi[kp][1], plo[kp][1]);
            split_pair(p[4], p[5], phi[kp][2], plo[kp][2]);
            split_pair(p[6], p[7], phi[kp][3], plo[kp][3]);
        }

        #pragma unroll
        for (int kp = 0; kp < 8; kp++) {
            #pragma unroll
            for (int jp = 0; jp < 4; jp++) {
                int row = jp * 16 + row_off;
                int chunk = kp * 2 + khalf;
                uint32_t off = (uint32_t)(row * 256 + ((chunk ^ (row & 7)) << 4));
                uint32_t vh4[4], vl4[4];
                ldsm4(vh4, base + AT_VH + off);
                ldsm4(vl4, base + AT_VL + off);
                mma16816(oacc[2*jp],   phi[kp], vh4);
                mma16816(oacc[2*jp],   plo[kp], vh4);
                mma16816(oacc[2*jp],   phi[kp], vl4);
                mma16816(oacc[2*jp+1], phi[kp], vh4 + 2);
                mma16816(oacc[2*jp+1], plo[kp], vh4 + 2);
                mma16816(oacc[2*jp+1], phi[kp], vl4 + 2);
            }
        }
        __syncthreads();   // all reads of buf (t&1) done before t+2 issues into it
    }

    l0 += __shfl_xor_sync(0xffffffffu, l0, 1);
    l0 += __shfl_xor_sync(0xffffffffu, l0, 2);
    l1 += __shfl_xor_sync(0xffffffffu, l1, 1);
    l1 += __shfl_xor_sync(0xffffffffu, l1, 2);
    const float inv0 = 1.0f / l0;
    const float inv1 = 1.0f / l1;

    const int s0 = q0 + w*16 + r0;
    float* o0 = out + ((size_t)b * SS + s0)     * (HH*DH) + h * DH;
    float* o1 = out + ((size_t)b * SS + s0 + 8) * (HH*DH) + h * DH;
    #pragma unroll
    for (int j = 0; j < 8; j++) {
        int col = j * 8 + cq;
        float2 w0 = make_float2(oacc[j][0] * inv0, oacc[j][1] * inv0);
        float2 w1 = make_float2(oacc[j][2] * inv1, oacc[j][3] * inv1);
        *(float2*)(o0 + col) = w0;
        *(float2*)(o1 + col) = w1;
    }
}

// ---------------------------------------------------------------------------
extern "C" void kernel_launch(void* const* d_in, const int* in_sizes, int n_in,
                              void* d_out, int out_size)
{
    const float* hs   = (const float*)d_in[0];
    const int*   mask = (const int*)  d_in[1];
    const float* Wq   = (const float*)d_in[2];
    const float* bq   = (const float*)d_in[3];
    const float* Wk   = (const float*)d_in[4];
    const float* bk   = (const float*)d_in[5];
    float* out = (float*)d_out;

    split_hs<<<(MROWS*DD) / (256 * 8), 256>>>(hs);          // 2048 blocks
    dim3 wgrid(DD / 64, DD / 64, 2);                        // (16,16,2)
    split_w<<<wgrid, 256>>>(Wq, Wk);

    cudaFuncSetAttribute(proj_gemm, cudaFuncAttributeMaxDynamicSharedMemorySize, PG_SMEM);
    dim3 pgrid(DD / 128, MROWS / 128, 2);                   // (8,32,2)
    proj_gemm<<<pgrid, 256, PG_SMEM>>>(bq, bk);

    split_k<<<(BB*HH*SS*DH) / (128 * 8), 128>>>();
    dim3 tgrid(SS / 64, BB * HH);
    transpose_v<<<tgrid, 256>>>();

    cudaFuncSetAttribute(attn, cudaFuncAttributeMaxDynamicSharedMemorySize, ATTN_SMEM);
    dim3 agrid(SS / 128, BB * HH);                          // (16,32)
    attn<<<agrid, 256, ATTN_SMEM>>>(mask, out);
}